// round 2
// baseline (speedup 1.0000x reference)
#include <cuda_runtime.h>

#define BB 16
#define TT 4096
#define DD 512
#define NROWS (BB*TT)

// PAD=10, BOS=11, EOS=12, ROW=13, SEP=14; digits 0..9

__device__ unsigned char g_rc[NROWS * 2];   // packed (r, c) per position
__device__ float g_srow[30 * DD];
__device__ float g_scol[30 * DD];

// Transition-function monoid element for the 2D-id state machine.
// Applied to state (g,r,c): g'=g?g1:g0 ; r'=rC?rV:r+rV ; c' per g-branch.
struct F { int g0, g1, rC, rV, c0C, c0, c1C, c1; };

__device__ __forceinline__ F fidentity() {
    F f; f.g0 = 0; f.g1 = 1; f.rC = 0; f.rV = 0;
    f.c0C = 0; f.c0 = 0; f.c1C = 0; f.c1 = 0; return f;
}

// compose(a,b) = "apply a first, then b"
__device__ __forceinline__ F fcompose(const F& a, const F& b) {
    F r;
    r.g0 = a.g0 ? b.g1 : b.g0;
    r.g1 = a.g1 ? b.g1 : b.g0;
    r.rC = b.rC | a.rC;
    r.rV = b.rC ? b.rV : a.rV + b.rV;
    int bC0 = a.g0 ? b.c1C : b.c0C;
    int bV0 = a.g0 ? b.c1  : b.c0;
    r.c0C = bC0 | a.c0C;
    r.c0  = bC0 ? bV0 : a.c0 + bV0;
    int bC1 = a.g1 ? b.c1C : b.c0C;
    int bV1 = a.g1 ? b.c1  : b.c0;
    r.c1C = bC1 | a.c1C;
    r.c1  = bC1 ? bV1 : a.c1 + bV1;
    return r;
}

__device__ __forceinline__ F fshfl_up(const F& f, int off) {
    F r;
    r.g0  = __shfl_up_sync(0xffffffffu, f.g0,  off);
    r.g1  = __shfl_up_sync(0xffffffffu, f.g1,  off);
    r.rC  = __shfl_up_sync(0xffffffffu, f.rC,  off);
    r.rV  = __shfl_up_sync(0xffffffffu, f.rV,  off);
    r.c0C = __shfl_up_sync(0xffffffffu, f.c0C, off);
    r.c0  = __shfl_up_sync(0xffffffffu, f.c0,  off);
    r.c1C = __shfl_up_sync(0xffffffffu, f.c1C, off);
    r.c1  = __shfl_up_sync(0xffffffffu, f.c1,  off);
    return r;
}

// ---------------------------------------------------------------------------
// Prep kernel: blocks 0..15 = per-sequence 2D-id scan (512 thr, 8 tok/thr,
// shuffle-scan combine); blocks 16..79 = srow/scol precompute (8 e's/block).
// ---------------------------------------------------------------------------
__global__ void __launch_bounds__(512) prep_kernel(
    const int* __restrict__ ids,
    const float* __restrict__ row_tab,   // (30, 256)
    const float* __restrict__ col_tab,   // (30, 256)
    const float* __restrict__ W)         // (512, 512) e-major
{
    __shared__ union SM {
        struct { int toks[TT]; F warpTot[16]; F warpPre[16]; } s;
        float w[8 * DD];
    } sm;

    const int tid = threadIdx.x;

    if (blockIdx.x < 16) {
        // ================= SCAN =================
        const int b = blockIdx.x;
        const int* base = ids + b * TT;

        // stage tokens coalesced
        #pragma unroll
        for (int i = 0; i < 8; i++) sm.s.toks[tid + i * 512] = base[tid + i * 512];
        __syncthreads();

        const int* my = sm.s.toks + tid * 8;

        // ---- Pass A: per-thread chunk summary ----
        F f = fidentity();
        #pragma unroll
        for (int j = 0; j < 8; j++) {
            int tok = my[j];
            int bos = (tok == 11), sep = (tok == 14), rw = (tok == 13);
            int end = (tok == 12) | (tok == 10);
            int dig = (tok <= 9);
            if (bos | sep) { f.rC = 1; f.rV = 0; }
            else if (rw) f.rV++;
            {
                int gc = f.g0 & dig;
                if (bos | sep | rw) { f.c0C = 1; f.c0 = 0; }
                else if (gc) f.c0++;
                f.g0 = bos ? 1 : (end ? 0 : f.g0);
            }
            {
                int gc = f.g1 & dig;
                if (bos | sep | rw) { f.c1C = 1; f.c1 = 0; }
                else if (gc) f.c1++;
                f.g1 = bos ? 1 : (end ? 0 : f.g1);
            }
        }

        // ---- Warp inclusive scan over summaries ----
        const int lane = tid & 31;
        const int wid = tid >> 5;
        F inc = f;
        #pragma unroll
        for (int off = 1; off < 32; off <<= 1) {
            F prev = fshfl_up(inc, off);
            if (lane >= off) inc = fcompose(prev, inc);
        }
        if (lane == 31) sm.s.warpTot[wid] = inc;
        __syncthreads();

        // ---- Serial exclusive prefix over 16 warp totals ----
        if (tid == 0) {
            F p = fidentity();
            #pragma unroll
            for (int i = 0; i < 16; i++) {
                sm.s.warpPre[i] = p;
                p = fcompose(p, sm.s.warpTot[i]);
            }
        }
        __syncthreads();

        // ---- Entry state = exclusive prefix applied to (g=0,r=0,c=0) ----
        F wex = fshfl_up(inc, 1);
        F ex = (lane > 0) ? fcompose(sm.s.warpPre[wid], wex) : sm.s.warpPre[wid];
        int g = ex.g0, r = ex.rV, c = ex.c0;

        // ---- Pass B: replay + emit ----
        unsigned int buf[4];
        #pragma unroll
        for (int j = 0; j < 8; j++) {
            int tok = my[j];
            int bos = (tok == 11), sep = (tok == 14), rw = (tok == 13);
            int end = (tok == 12) | (tok == 10);
            int dig = (tok <= 9);
            int gc = g & dig;
            unsigned int er = gc ? (unsigned)min(r, 29) : 0u;
            unsigned int ec = gc ? (unsigned)min(c, 29) : 0u;
            unsigned int pair = er | (ec << 8);
            if (j & 1) buf[j >> 1] |= (pair << 16);
            else       buf[j >> 1] = pair;
            g = bos ? 1 : (end ? 0 : g);
            r = (bos | sep) ? 0 : (rw ? r + 1 : r);
            c = (bos | sep | rw) ? 0 : (gc ? c + 1 : c);
        }
        *(uint4*)(g_rc + (size_t)(b * TT + tid * 8) * 2) = *(const uint4*)buf;
    } else {
        // ================= PRECOMPUTE srow/scol =================
        const int grp = tid >> 6;          // 8 groups of 64 threads
        const int wi  = tid & 63;
        const int e = (blockIdx.x - 16) * 8 + grp;

        float* wsh = sm.w + grp * DD;
        for (int i = wi; i < DD; i += 64) wsh[i] = W[(size_t)e * DD + i];
        __syncthreads();

        if (wi < 30) {
            const float* tr = row_tab + wi * 256;
            float s0 = 0.f, s1 = 0.f, s2 = 0.f, s3 = 0.f;
            #pragma unroll 4
            for (int d = 0; d < 256; d += 4) {
                s0 = fmaf(tr[d + 0], wsh[d + 0], s0);
                s1 = fmaf(tr[d + 1], wsh[d + 1], s1);
                s2 = fmaf(tr[d + 2], wsh[d + 2], s2);
                s3 = fmaf(tr[d + 3], wsh[d + 3], s3);
            }
            g_srow[wi * DD + e] = (s0 + s1) + (s2 + s3);
        } else if (wi >= 32 && wi < 62) {
            const int r = wi - 32;
            const float* tc = col_tab + r * 256;
            float s0 = 0.f, s1 = 0.f, s2 = 0.f, s3 = 0.f;
            #pragma unroll 4
            for (int d = 0; d < 256; d += 4) {
                s0 = fmaf(tc[d + 0], wsh[256 + d + 0], s0);
                s1 = fmaf(tc[d + 1], wsh[256 + d + 1], s1);
                s2 = fmaf(tc[d + 2], wsh[256 + d + 2], s2);
                s3 = fmaf(tc[d + 3], wsh[256 + d + 3], s3);
            }
            g_scol[r * DD + e] = (s0 + s1) + (s2 + s3);
        }
    }
}

// ---------------------------------------------------------------------------
// Main kernel: one block per t (4096 blocks, 512 thr). pos row staged in
// shared once, 16 warps handle the 16 batches. Fused gather+add+mask+LN.
// ---------------------------------------------------------------------------
__global__ void __launch_bounds__(512) main_kernel(
    const int* __restrict__ ids,
    const float* __restrict__ tok_tab,   // (15, 512)
    const float* __restrict__ pos_tab,   // (4096, 512)
    const float* __restrict__ gamma,
    const float* __restrict__ beta,
    float* __restrict__ out)
{
    __shared__ __align__(16) float pos_sh[DD];

    const int t = blockIdx.x;
    const int lane = threadIdx.x & 31;
    const int b = threadIdx.x >> 5;

    pos_sh[threadIdx.x] = pos_tab[(size_t)t * DD + threadIdx.x];
    __syncthreads();

    const int row = b * TT + t;
    const int tok = ids[row];
    const unsigned int pr = ((const unsigned short*)g_rc)[row];
    const int r = pr & 0xff;
    const int c = (pr >> 8) & 0xff;
    const float mask = (tok <= 9) ? 1.f : 0.f;

    const float4* tp = (const float4*)(tok_tab + (size_t)tok * DD);
    const float4* pp = (const float4*)pos_sh;
    const float4* rp = (const float4*)(g_srow + r * DD);
    const float4* cp = (const float4*)(g_scol + c * DD);

    float4 x[4];
    float sum = 0.f, sq = 0.f;
    #pragma unroll
    for (int i = 0; i < 4; i++) {
        const int idx = lane + i * 32;
        float4 a = tp[idx];
        float4 p = pp[idx];
        float4 rr = rp[idx];
        float4 cc = cp[idx];
        float4 v;
        v.x = fmaf(mask, rr.x + cc.x, a.x + p.x);
        v.y = fmaf(mask, rr.y + cc.y, a.y + p.y);
        v.z = fmaf(mask, rr.z + cc.z, a.z + p.z);
        v.w = fmaf(mask, rr.w + cc.w, a.w + p.w);
        x[i] = v;
        sum += (v.x + v.y) + (v.z + v.w);
        sq = fmaf(v.x, v.x, sq);
        sq = fmaf(v.y, v.y, sq);
        sq = fmaf(v.z, v.z, sq);
        sq = fmaf(v.w, v.w, sq);
    }

    #pragma unroll
    for (int o = 16; o > 0; o >>= 1) {
        sum += __shfl_xor_sync(0xffffffffu, sum, o);
        sq  += __shfl_xor_sync(0xffffffffu, sq,  o);
    }

    const float mu = sum * (1.f / (float)DD);
    const float var = sq * (1.f / (float)DD) - mu * mu;
    const float inv = rsqrtf(var + 1e-5f);

    float4* op = (float4*)(out + (size_t)row * DD);
    const float4* gp = (const float4*)gamma;
    const float4* bp = (const float4*)beta;
    #pragma unroll
    for (int i = 0; i < 4; i++) {
        const int idx = lane + i * 32;
        float4 gm = __ldg(gp + idx);
        float4 bt = __ldg(bp + idx);
        float4 v = x[i];
        v.x = fmaf((v.x - mu) * inv, gm.x, bt.x);
        v.y = fmaf((v.y - mu) * inv, gm.y, bt.y);
        v.z = fmaf((v.z - mu) * inv, gm.z, bt.z);
        v.w = fmaf((v.w - mu) * inv, gm.w, bt.w);
        __stcs(op + idx, v);
    }
}

// ---------------------------------------------------------------------------
extern "C" void kernel_launch(void* const* d_in, const int* in_sizes, int n_in,
                              void* d_out, int out_size) {
    const int*   ids   = (const int*)  d_in[0];
    const float* tokt  = (const float*)d_in[1];
    const float* post  = (const float*)d_in[2];
    const float* rowt  = (const float*)d_in[3];
    const float* colt  = (const float*)d_in[4];
    const float* W     = (const float*)d_in[5];
    const float* gamma = (const float*)d_in[6];
    const float* beta  = (const float*)d_in[7];
    float* out = (float*)d_out;
    (void)in_sizes; (void)n_in; (void)out_size;

    prep_kernel<<<80, 512>>>(ids, rowt, colt, W);
    main_kernel<<<TT, 512>>>(ids, tokt, post, gamma, beta, out);
}

// round 3
// speedup vs baseline: 1.9805x; 1.9805x over previous
#include <cuda_runtime.h>

#define BB 16
#define TT 4096
#define DD 512
#define NROWS (BB*TT)

// PAD=10, BOS=11, EOS=12, ROW=13, SEP=14; digits 0..9

__device__ unsigned char g_rc[NROWS * 2];   // packed (r, c) per position
__device__ float g_srow[30 * DD];
__device__ float g_scol[30 * DD];

// Transition-function monoid for the 2D-id state machine.
struct F { int g0, g1, rC, rV, c0C, c0, c1C, c1; };

__device__ __forceinline__ F fidentity() {
    F f; f.g0 = 0; f.g1 = 1; f.rC = 0; f.rV = 0;
    f.c0C = 0; f.c0 = 0; f.c1C = 0; f.c1 = 0; return f;
}

// compose(a,b) = "apply a first, then b"
__device__ __forceinline__ F fcompose(const F& a, const F& b) {
    F r;
    r.g0 = a.g0 ? b.g1 : b.g0;
    r.g1 = a.g1 ? b.g1 : b.g0;
    r.rC = b.rC | a.rC;
    r.rV = b.rC ? b.rV : a.rV + b.rV;
    int bC0 = a.g0 ? b.c1C : b.c0C;
    int bV0 = a.g0 ? b.c1  : b.c0;
    r.c0C = bC0 | a.c0C;
    r.c0  = bC0 ? bV0 : a.c0 + bV0;
    int bC1 = a.g1 ? b.c1C : b.c0C;
    int bV1 = a.g1 ? b.c1  : b.c0;
    r.c1C = bC1 | a.c1C;
    r.c1  = bC1 ? bV1 : a.c1 + bV1;
    return r;
}

__device__ __forceinline__ F fshfl_up(const F& f, int off) {
    F r;
    r.g0  = __shfl_up_sync(0xffffffffu, f.g0,  off);
    r.g1  = __shfl_up_sync(0xffffffffu, f.g1,  off);
    r.rC  = __shfl_up_sync(0xffffffffu, f.rC,  off);
    r.rV  = __shfl_up_sync(0xffffffffu, f.rV,  off);
    r.c0C = __shfl_up_sync(0xffffffffu, f.c0C, off);
    r.c0  = __shfl_up_sync(0xffffffffu, f.c0,  off);
    r.c1C = __shfl_up_sync(0xffffffffu, f.c1C, off);
    r.c1  = __shfl_up_sync(0xffffffffu, f.c1,  off);
    return r;
}

// ---------------------------------------------------------------------------
// Kernel 1: 2D-id scan. One block per sequence, 512 thr, 8 tok/thr,
// warp shuffle-scan over chunk summaries, then replay + emit.
// ---------------------------------------------------------------------------
__global__ void __launch_bounds__(512) scan_kernel(const int* __restrict__ ids) {
    __shared__ int toks[TT];
    __shared__ F warpTot[16];
    __shared__ F warpPre[16];

    const int b = blockIdx.x;
    const int tid = threadIdx.x;
    const int* base = ids + b * TT;

    #pragma unroll
    for (int i = 0; i < 8; i++) toks[tid + i * 512] = base[tid + i * 512];
    __syncthreads();

    const int* my = toks + tid * 8;

    // ---- Pass A: per-thread chunk summary ----
    F f = fidentity();
    #pragma unroll
    for (int j = 0; j < 8; j++) {
        int tok = my[j];
        int bos = (tok == 11), sep = (tok == 14), rw = (tok == 13);
        int end = (tok == 12) | (tok == 10);
        int dig = (tok <= 9);
        if (bos | sep) { f.rC = 1; f.rV = 0; }
        else if (rw) f.rV++;
        {
            int gc = f.g0 & dig;
            if (bos | sep | rw) { f.c0C = 1; f.c0 = 0; }
            else if (gc) f.c0++;
            f.g0 = bos ? 1 : (end ? 0 : f.g0);
        }
        {
            int gc = f.g1 & dig;
            if (bos | sep | rw) { f.c1C = 1; f.c1 = 0; }
            else if (gc) f.c1++;
            f.g1 = bos ? 1 : (end ? 0 : f.g1);
        }
    }

    // ---- Warp inclusive scan ----
    const int lane = tid & 31;
    const int wid = tid >> 5;
    F inc = f;
    #pragma unroll
    for (int off = 1; off < 32; off <<= 1) {
        F prev = fshfl_up(inc, off);
        if (lane >= off) inc = fcompose(prev, inc);
    }
    if (lane == 31) warpTot[wid] = inc;
    __syncthreads();

    if (tid == 0) {
        F p = fidentity();
        #pragma unroll
        for (int i = 0; i < 16; i++) {
            warpPre[i] = p;
            p = fcompose(p, warpTot[i]);
        }
    }
    __syncthreads();

    F wex = fshfl_up(inc, 1);
    F ex = (lane > 0) ? fcompose(warpPre[wid], wex) : warpPre[wid];
    int g = ex.g0, r = ex.rV, c = ex.c0;   // applied to initial state (0,0,0)

    // ---- Pass B: replay + emit ----
    unsigned int buf[4];
    #pragma unroll
    for (int j = 0; j < 8; j++) {
        int tok = my[j];
        int bos = (tok == 11), sep = (tok == 14), rw = (tok == 13);
        int end = (tok == 12) | (tok == 10);
        int dig = (tok <= 9);
        int gc = g & dig;
        unsigned int er = gc ? (unsigned)min(r, 29) : 0u;
        unsigned int ec = gc ? (unsigned)min(c, 29) : 0u;
        unsigned int pair = er | (ec << 8);
        if (j & 1) buf[j >> 1] |= (pair << 16);
        else       buf[j >> 1] = pair;
        g = bos ? 1 : (end ? 0 : g);
        r = (bos | sep) ? 0 : (rw ? r + 1 : r);
        c = (bos | sep | rw) ? 0 : (gc ? c + 1 : c);
    }
    *(uint4*)(g_rc + (size_t)(b * TT + tid * 8) * 2) = *(const uint4*)buf;
}

// ---------------------------------------------------------------------------
// Kernel 2: srow/scol precompute, COALESCED along d.
// 60 blocks (30 row + 30 col) x 512 thr. Block stages its 256-float table row
// in shared; each warp computes 32 output e's: lanes split d (coalesced
// float4 loads from W), warp-shuffle reduction.
// ---------------------------------------------------------------------------
__global__ void __launch_bounds__(512) precompute_kernel(
    const float* __restrict__ row_tab,   // (30, 256)
    const float* __restrict__ col_tab,   // (30, 256)
    const float* __restrict__ W)         // (512, 512) e-major
{
    __shared__ __align__(16) float tab[256];

    const int isCol = blockIdx.x >= 30;
    const int r = isCol ? blockIdx.x - 30 : blockIdx.x;
    const float* src = (isCol ? col_tab : row_tab) + r * 256;
    if (threadIdx.x < 256) tab[threadIdx.x] = src[threadIdx.x];
    __syncthreads();

    const int warp = threadIdx.x >> 5;
    const int lane = threadIdx.x & 31;
    const int off = isCol ? 256 : 0;
    float* dst = (isCol ? g_scol : g_srow) + r * DD;

    // thread-local slice of the table (conflict-free LDS.128)
    const float4 t0 = ((const float4*)tab)[lane * 2];
    const float4 t1 = ((const float4*)tab)[lane * 2 + 1];

    #pragma unroll 4
    for (int k = 0; k < 32; k++) {
        const int e = warp * 32 + k;
        const float4* wp = (const float4*)(W + (size_t)e * DD + off);
        float4 a = wp[lane * 2];
        float4 b2 = wp[lane * 2 + 1];
        float s = a.x * t0.x;
        s = fmaf(a.y, t0.y, s);
        s = fmaf(a.z, t0.z, s);
        s = fmaf(a.w, t0.w, s);
        s = fmaf(b2.x, t1.x, s);
        s = fmaf(b2.y, t1.y, s);
        s = fmaf(b2.z, t1.z, s);
        s = fmaf(b2.w, t1.w, s);
        #pragma unroll
        for (int o = 16; o > 0; o >>= 1)
            s += __shfl_xor_sync(0xffffffffu, s, o);
        if (lane == 0) dst[e] = s;
    }
}

// ---------------------------------------------------------------------------
// Kernel 3: fused gather + add + mask + LayerNorm. One block per t, 16 warps
// = 16 batches. pos/gamma/beta staged in shared once per block.
// ---------------------------------------------------------------------------
__global__ void __launch_bounds__(512) main_kernel(
    const int* __restrict__ ids,
    const float* __restrict__ tok_tab,   // (15, 512)
    const float* __restrict__ pos_tab,   // (4096, 512)
    const float* __restrict__ gamma,
    const float* __restrict__ beta,
    float* __restrict__ out)
{
    __shared__ __align__(16) float pos_sh[DD];
    __shared__ __align__(16) float g_sh[DD];
    __shared__ __align__(16) float b_sh[DD];

    const int t = blockIdx.x;
    const int lane = threadIdx.x & 31;
    const int b = threadIdx.x >> 5;

    pos_sh[threadIdx.x] = pos_tab[(size_t)t * DD + threadIdx.x];
    g_sh[threadIdx.x] = gamma[threadIdx.x];
    b_sh[threadIdx.x] = beta[threadIdx.x];
    __syncthreads();

    const int row = b * TT + t;
    const int tok = ids[row];
    const unsigned int pr = ((const unsigned short*)g_rc)[row];
    const int r = pr & 0xff;
    const int c = (pr >> 8) & 0xff;
    const float mask = (tok <= 9) ? 1.f : 0.f;

    const float4* tp = (const float4*)(tok_tab + (size_t)tok * DD);
    const float4* pp = (const float4*)pos_sh;
    const float4* rp = (const float4*)(g_srow + r * DD);
    const float4* cp = (const float4*)(g_scol + c * DD);

    float4 x[4];
    float sum = 0.f, sq = 0.f;
    #pragma unroll
    for (int i = 0; i < 4; i++) {
        const int idx = lane + i * 32;
        float4 a = tp[idx];
        float4 p = pp[idx];
        float4 rr = rp[idx];
        float4 cc = cp[idx];
        float4 v;
        v.x = fmaf(mask, rr.x + cc.x, a.x + p.x);
        v.y = fmaf(mask, rr.y + cc.y, a.y + p.y);
        v.z = fmaf(mask, rr.z + cc.z, a.z + p.z);
        v.w = fmaf(mask, rr.w + cc.w, a.w + p.w);
        x[i] = v;
        sum += (v.x + v.y) + (v.z + v.w);
        sq = fmaf(v.x, v.x, sq);
        sq = fmaf(v.y, v.y, sq);
        sq = fmaf(v.z, v.z, sq);
        sq = fmaf(v.w, v.w, sq);
    }

    #pragma unroll
    for (int o = 16; o > 0; o >>= 1) {
        sum += __shfl_xor_sync(0xffffffffu, sum, o);
        sq  += __shfl_xor_sync(0xffffffffu, sq,  o);
    }

    const float mu = sum * (1.f / (float)DD);
    const float var = sq * (1.f / (float)DD) - mu * mu;
    const float inv = rsqrtf(var + 1e-5f);

    float4* op = (float4*)(out + (size_t)row * DD);
    const float4* gp = (const float4*)g_sh;
    const float4* bp = (const float4*)b_sh;
    #pragma unroll
    for (int i = 0; i < 4; i++) {
        const int idx = lane + i * 32;
        float4 gm = gp[idx];
        float4 bt = bp[idx];
        float4 v = x[i];
        v.x = fmaf((v.x - mu) * inv, gm.x, bt.x);
        v.y = fmaf((v.y - mu) * inv, gm.y, bt.y);
        v.z = fmaf((v.z - mu) * inv, gm.z, bt.z);
        v.w = fmaf((v.w - mu) * inv, gm.w, bt.w);
        __stcs(op + idx, v);
    }
}

// ---------------------------------------------------------------------------
extern "C" void kernel_launch(void* const* d_in, const int* in_sizes, int n_in,
                              void* d_out, int out_size) {
    const int*   ids   = (const int*)  d_in[0];
    const float* tokt  = (const float*)d_in[1];
    const float* post  = (const float*)d_in[2];
    const float* rowt  = (const float*)d_in[3];
    const float* colt  = (const float*)d_in[4];
    const float* W     = (const float*)d_in[5];
    const float* gamma = (const float*)d_in[6];
    const float* beta  = (const float*)d_in[7];
    float* out = (float*)d_out;
    (void)in_sizes; (void)n_in; (void)out_size;

    scan_kernel<<<BB, 512>>>(ids);
    precompute_kernel<<<60, 512>>>(rowt, colt, W);
    main_kernel<<<TT, 512>>>(ids, tokt, post, gamma, beta, out);
}

// round 4
// speedup vs baseline: 2.4379x; 1.2309x over previous
#include <cuda_runtime.h>

#define BB 16
#define TT 4096
#define DD 512
#define NROWS (BB*TT)

// PAD=10, BOS=11, EOS=12, ROW=13, SEP=14; digits 0..9

__device__ unsigned char g_rc[NROWS * 2];   // packed (r, c) per position
__device__ float g_srow[30 * DD];
__device__ float g_scol[30 * DD];

// ---------------------------------------------------------------------------
// Packed transition-function monoid (2 words):
//   a: bit0 g0out, bit1 g1out, bit2 rConst, bit3 c0Const, bit4 c1Const,
//      bits[8..] rVal (<= 4096, fits 13 bits)
//   b: bits[0:16) c0Val, bits[16:32) c1Val
// ---------------------------------------------------------------------------
struct P { unsigned a, b; };

__device__ __forceinline__ P pidentity() { P p; p.a = 2u; p.b = 0u; return p; }

// compose(x, y) = apply x first, then y
__device__ __forceinline__ P pcompose(P x, P y) {
    unsigned xg0 = x.a & 1u, xg1 = (x.a >> 1) & 1u;
    unsigned yg0 = y.a & 1u, yg1 = (y.a >> 1) & 1u;
    unsigned g0 = xg0 ? yg1 : yg0;
    unsigned g1 = xg1 ? yg1 : yg0;
    unsigned yrC = y.a & 4u;
    unsigned rV = yrC ? (y.a >> 8) : ((x.a >> 8) + (y.a >> 8));
    unsigned rC = (x.a & 4u) | yrC;
    unsigned xc0C = (x.a >> 3) & 1u, xc1C = (x.a >> 4) & 1u;
    unsigned yc0C = (y.a >> 3) & 1u, yc1C = (y.a >> 4) & 1u;
    unsigned xc0 = x.b & 0xffffu, xc1 = x.b >> 16;
    unsigned yc0 = y.b & 0xffffu, yc1 = y.b >> 16;
    unsigned bC0 = xg0 ? yc1C : yc0C;
    unsigned bV0 = xg0 ? yc1  : yc0;
    unsigned c0C = bC0 | xc0C;
    unsigned c0  = bC0 ? bV0 : xc0 + bV0;
    unsigned bC1 = xg1 ? yc1C : yc0C;
    unsigned bV1 = xg1 ? yc1  : yc0;
    unsigned c1C = bC1 | xc1C;
    unsigned c1  = bC1 ? bV1 : xc1 + bV1;
    P r;
    r.a = g0 | (g1 << 1) | rC | (c0C << 3) | (c1C << 4) | (rV << 8);
    r.b = c0 | (c1 << 16);
    return r;
}

__device__ __forceinline__ P pshfl_up(P p, int off) {
    P r;
    r.a = __shfl_up_sync(0xffffffffu, p.a, off);
    r.b = __shfl_up_sync(0xffffffffu, p.b, off);
    return r;
}

// ---------------------------------------------------------------------------
// Prep kernel (fused): blocks 0..15 = per-sequence 2D-id scan;
// blocks 16..75 = srow/scol precompute (coalesced along d).
// ---------------------------------------------------------------------------
__global__ void __launch_bounds__(512) prep_kernel(
    const int* __restrict__ ids,
    const float* __restrict__ row_tab,   // (30, 256)
    const float* __restrict__ col_tab,   // (30, 256)
    const float* __restrict__ W)         // (512, 512) e-major
{
    __shared__ union SM {
        struct { int toks[TT]; P warpTot[16]; P warpPre[16]; } s;
        float tab[256];
    } sm;

    const int tid = threadIdx.x;

    if (blockIdx.x < 16) {
        // ================= SCAN =================
        const int b = blockIdx.x;
        const int* base = ids + b * TT;

        #pragma unroll
        for (int i = 0; i < 8; i++) sm.s.toks[tid + i * 512] = base[tid + i * 512];
        __syncthreads();

        const int* my = sm.s.toks + tid * 8;

        // ---- Pass A: per-thread chunk summary (unpacked locals) ----
        int fg0 = 0, fg1 = 1, frC = 0, frV = 0;
        int fc0C = 0, fc0 = 0, fc1C = 0, fc1 = 0;
        #pragma unroll
        for (int j = 0; j < 8; j++) {
            int tok = my[j];
            int bos = (tok == 11), sep = (tok == 14), rw = (tok == 13);
            int end = (tok == 12) | (tok == 10);
            int dig = (tok <= 9);
            if (bos | sep) { frC = 1; frV = 0; }
            else if (rw) frV++;
            {
                int gc = fg0 & dig;
                if (bos | sep | rw) { fc0C = 1; fc0 = 0; }
                else if (gc) fc0++;
                fg0 = bos ? 1 : (end ? 0 : fg0);
            }
            {
                int gc = fg1 & dig;
                if (bos | sep | rw) { fc1C = 1; fc1 = 0; }
                else if (gc) fc1++;
                fg1 = bos ? 1 : (end ? 0 : fg1);
            }
        }
        P inc;
        inc.a = (unsigned)fg0 | ((unsigned)fg1 << 1) | ((unsigned)frC << 2)
              | ((unsigned)fc0C << 3) | ((unsigned)fc1C << 4) | ((unsigned)frV << 8);
        inc.b = (unsigned)fc0 | ((unsigned)fc1 << 16);

        // ---- Warp inclusive scan (2 shuffles/step) ----
        const int lane = tid & 31;
        const int wid = tid >> 5;
        #pragma unroll
        for (int off = 1; off < 32; off <<= 1) {
            P prev = pshfl_up(inc, off);
            if (lane >= off) inc = pcompose(prev, inc);
        }
        if (lane == 31) sm.s.warpTot[wid] = inc;
        __syncthreads();

        if (tid == 0) {
            P p = pidentity();
            #pragma unroll
            for (int i = 0; i < 16; i++) {
                sm.s.warpPre[i] = p;
                p = pcompose(p, sm.s.warpTot[i]);
            }
        }
        __syncthreads();

        P wex = pshfl_up(inc, 1);
        P ex = (lane > 0) ? pcompose(sm.s.warpPre[wid], wex) : sm.s.warpPre[wid];
        // apply to initial state (g=0, r=0, c=0): take g0-branch
        int g = (int)(ex.a & 1u);
        int r = (int)(ex.a >> 8);
        int c = (int)(ex.b & 0xffffu);

        // ---- Pass B: replay + emit ----
        unsigned int buf[4];
        #pragma unroll
        for (int j = 0; j < 8; j++) {
            int tok = my[j];
            int bos = (tok == 11), sep = (tok == 14), rw = (tok == 13);
            int end = (tok == 12) | (tok == 10);
            int dig = (tok <= 9);
            int gc = g & dig;
            unsigned int er = gc ? (unsigned)min(r, 29) : 0u;
            unsigned int ec = gc ? (unsigned)min(c, 29) : 0u;
            unsigned int pair = er | (ec << 8);
            if (j & 1) buf[j >> 1] |= (pair << 16);
            else       buf[j >> 1] = pair;
            g = bos ? 1 : (end ? 0 : g);
            r = (bos | sep) ? 0 : (rw ? r + 1 : r);
            c = (bos | sep | rw) ? 0 : (gc ? c + 1 : c);
        }
        *(uint4*)(g_rc + (size_t)(b * TT + tid * 8) * 2) = *(const uint4*)buf;
    } else {
        // ================= PRECOMPUTE srow/scol =================
        const int bi = blockIdx.x - 16;
        const int isCol = bi >= 30;
        const int r = isCol ? bi - 30 : bi;
        const float* src = (isCol ? col_tab : row_tab) + r * 256;
        if (tid < 256) sm.tab[tid] = src[tid];
        __syncthreads();

        const int warp = tid >> 5;
        const int lane = tid & 31;
        const int off = isCol ? 256 : 0;
        float* dst = (isCol ? g_scol : g_srow) + r * DD;

        const float4 t0 = ((const float4*)sm.tab)[lane * 2];
        const float4 t1 = ((const float4*)sm.tab)[lane * 2 + 1];

        #pragma unroll 4
        for (int k = 0; k < 32; k++) {
            const int e = warp * 32 + k;
            const float4* wp = (const float4*)(W + (size_t)e * DD + off);
            float4 a = wp[lane * 2];
            float4 b2 = wp[lane * 2 + 1];
            float s = a.x * t0.x;
            s = fmaf(a.y, t0.y, s);
            s = fmaf(a.z, t0.z, s);
            s = fmaf(a.w, t0.w, s);
            s = fmaf(b2.x, t1.x, s);
            s = fmaf(b2.y, t1.y, s);
            s = fmaf(b2.z, t1.z, s);
            s = fmaf(b2.w, t1.w, s);
            #pragma unroll
            for (int o = 16; o > 0; o >>= 1)
                s += __shfl_xor_sync(0xffffffffu, s, o);
            if (lane == 0) dst[e] = s;
        }
    }
}

// ---------------------------------------------------------------------------
// Main kernel: barrier-free, warp-per-row. 256 thr = 8 warps; 2 blocks per t
// cover the 16 batches. pos/gamma/beta/tables shared across warps via L1.
// ---------------------------------------------------------------------------
__global__ void __launch_bounds__(256) main_kernel(
    const int* __restrict__ ids,
    const float* __restrict__ tok_tab,   // (15, 512)
    const float* __restrict__ pos_tab,   // (4096, 512)
    const float* __restrict__ gamma,
    const float* __restrict__ beta,
    float* __restrict__ out)
{
    const int warp = threadIdx.x >> 5;
    const int lane = threadIdx.x & 31;
    const int t = blockIdx.x >> 1;
    const int b = ((blockIdx.x & 1) << 3) | warp;
    const int row = b * TT + t;

    const int tok = __ldg(ids + row);
    const unsigned int pr = __ldg((const unsigned short*)g_rc + row);
    const int r = pr & 0xff;
    const int c = (pr >> 8) & 0xff;
    const float mask = (tok <= 9) ? 1.f : 0.f;

    const float4* tp = (const float4*)(tok_tab + (size_t)tok * DD);
    const float4* pp = (const float4*)(pos_tab + (size_t)t * DD);
    const float4* rp = (const float4*)(g_srow + r * DD);
    const float4* cp = (const float4*)(g_scol + c * DD);

    float4 x[4];
    float sum = 0.f, sq = 0.f;
    #pragma unroll
    for (int i = 0; i < 4; i++) {
        const int idx = lane + i * 32;
        float4 a = __ldg(tp + idx);
        float4 p = __ldg(pp + idx);
        float4 rr = __ldg(rp + idx);
        float4 cc = __ldg(cp + idx);
        float4 v;
        v.x = fmaf(mask, rr.x + cc.x, a.x + p.x);
        v.y = fmaf(mask, rr.y + cc.y, a.y + p.y);
        v.z = fmaf(mask, rr.z + cc.z, a.z + p.z);
        v.w = fmaf(mask, rr.w + cc.w, a.w + p.w);
        x[i] = v;
        sum += (v.x + v.y) + (v.z + v.w);
        sq = fmaf(v.x, v.x, sq);
        sq = fmaf(v.y, v.y, sq);
        sq = fmaf(v.z, v.z, sq);
        sq = fmaf(v.w, v.w, sq);
    }

    #pragma unroll
    for (int o = 16; o > 0; o >>= 1) {
        sum += __shfl_xor_sync(0xffffffffu, sum, o);
        sq  += __shfl_xor_sync(0xffffffffu, sq,  o);
    }

    const float mu = sum * (1.f / (float)DD);
    const float var = sq * (1.f / (float)DD) - mu * mu;
    const float inv = rsqrtf(var + 1e-5f);

    float4* op = (float4*)(out + (size_t)row * DD);
    const float4* gp = (const float4*)gamma;
    const float4* bp = (const float4*)beta;
    #pragma unroll
    for (int i = 0; i < 4; i++) {
        const int idx = lane + i * 32;
        float4 gm = __ldg(gp + idx);
        float4 bt = __ldg(bp + idx);
        float4 v = x[i];
        v.x = fmaf((v.x - mu) * inv, gm.x, bt.x);
        v.y = fmaf((v.y - mu) * inv, gm.y, bt.y);
        v.z = fmaf((v.z - mu) * inv, gm.z, bt.z);
        v.w = fmaf((v.w - mu) * inv, gm.w, bt.w);
        __stcs(op + idx, v);
    }
}

// ---------------------------------------------------------------------------
extern "C" void kernel_launch(void* const* d_in, const int* in_sizes, int n_in,
                              void* d_out, int out_size) {
    const int*   ids   = (const int*)  d_in[0];
    const float* tokt  = (const float*)d_in[1];
    const float* post  = (const float*)d_in[2];
    const float* rowt  = (const float*)d_in[3];
    const float* colt  = (const float*)d_in[4];
    const float* W     = (const float*)d_in[5];
    const float* gamma = (const float*)d_in[6];
    const float* beta  = (const float*)d_in[7];
    float* out = (float*)d_out;
    (void)in_sizes; (void)n_in; (void)out_size;

    prep_kernel<<<76, 512>>>(ids, rowt, colt, W);
    main_kernel<<<TT * 2, 256>>>(ids, tokt, post, gamma, beta, out);
}